// round 16
// baseline (speedup 1.0000x reference)
#include <cuda_runtime.h>
#include <cuda_fp16.h>
#include <cstdint>

// Problem constants: N=4096, D=128, S=32768, NUM_CLASS=500000.
#define DIM 128
#define MAX_S 32768
#define MAX_N 4096
#define NUM_CLASS_MAX 500000

// Scratch: fp16 operands + gathered fp32 bias.
static __device__ __half g_w[(size_t)MAX_S * DIM];
static __device__ __half g_x[(size_t)MAX_N * DIM];
static __device__ float g_bias[MAX_S];
static __device__ int g_ids_is64;

// ---------------------------------------------------------------------------
// Kernel 0a: reset dtype flag. Kernel 0b: parallel detect (benign-race store).
// ---------------------------------------------------------------------------
__global__ void init_flag_kernel() { g_ids_is64 = 1; }

__global__ void detect_ids_kernel(const void* __restrict__ ids, int S) {
    const long long* p = (const long long*)ids;
    int n64 = S / 2;
    int i = blockIdx.x * blockDim.x + threadIdx.x;
    int stride = gridDim.x * blockDim.x;
    int bad = 0;
    for (; i < n64; i += stride) {
        long long v = p[i];
        if (v < 0 || v >= NUM_CLASS_MAX) bad = 1;
    }
    if (__syncthreads_or(bad) && threadIdx.x == 0) g_ids_is64 = 0;
}

__device__ __forceinline__ long long read_id(const void* ids, int s) {
    long long id = g_ids_is64 ? ((const long long*)ids)[s]
                              : (long long)((const int*)ids)[s];
    if (id < 0 || id >= NUM_CLASS_MAX) id = 0;
    return id;
}

// ---------------------------------------------------------------------------
// Kernel 1 (fused): gather weight[ids]->g_w fp16 + bias; convert x->g_x fp16;
// ids pass-through into the output tail (runs BEFORE the GEMM).
// ---------------------------------------------------------------------------
__global__ void prep_kernel(const float* __restrict__ x,
                            const float* __restrict__ w,
                            const float* __restrict__ bias,
                            const void* __restrict__ ids,
                            void* out, long long base, long long extra,
                            int N, int S) {
    int warp = (blockIdx.x * blockDim.x + threadIdx.x) >> 5;
    int lane = threadIdx.x & 31;
    int nwarps = (gridDim.x * blockDim.x) >> 5;
    int total = S + N;
    for (int s = warp; s < total; s += nwarps) {
        const float4* src;
        __half2* dst;
        if (s < S) {
            long long id = read_id(ids, s);
            src = (const float4*)(w + (size_t)id * DIM);
            dst = (__half2*)(g_w + (size_t)s * DIM);
            if (lane == 0) g_bias[s] = bias[id];
        } else {
            int r = s - S;
            src = (const float4*)(x + (size_t)r * DIM);
            dst = (__half2*)(g_x + (size_t)r * DIM);
        }
        float4 v = src[lane];
        dst[lane * 2 + 0] = __float22half2_rn(make_float2(v.x, v.y));
        dst[lane * 2 + 1] = __float22half2_rn(make_float2(v.z, v.w));
    }
    if (extra > 0) {
        int gidx = blockIdx.x * blockDim.x + threadIdx.x;
        int gstride = gridDim.x * blockDim.x;
        for (int s = gidx; s < S; s += gstride) {
            long long id = read_id(ids, s);
            if (extra >= 2LL * S) {
                ((long long*)((float*)out + base))[s] = id;
            } else if (extra >= (long long)S) {
                ((float*)out)[base + s] = (float)id;
            }
        }
    }
}

// ---------------------------------------------------------------------------
// Kernel 2: fp16 GEMM, mma.m16n8k16 + ldmatrix, 256 threads (8 warps, 2x4),
// warp tile 64x32, 2 CTAs/SM (16 warps/SM). Each CTA: one resident A tile
// (128x128, 32KB) + FOUR consecutive 128-wide N-tiles with a 2x32KB B ring —
// B for tile j+1 streams while tile j computes; scattered st.cs.v2 epilogue.
// Rows hold full K=128 (256B); XOR-8 16B-block swizzle. (R13 config =
// measured-best GEMM, 158.3us.)
// ---------------------------------------------------------------------------
#define TM 128
#define TN 128
#define NJ 4                                  // N-tiles per CTA
#define A_BYTES (TM * DIM * 2)                // 32768
#define B_BYTES (TN * DIM * 2)                // 32768
#define SM_TOTAL (A_BYTES + 2 * B_BYTES)      // 98304

__device__ __forceinline__ void mma_f16(float c[4], const uint32_t a[4],
                                        const uint32_t b[2]) {
    asm volatile(
        "mma.sync.aligned.m16n8k16.row.col.f32.f16.f16.f32 "
        "{%0,%1,%2,%3}, {%4,%5,%6,%7}, {%8,%9}, {%0,%1,%2,%3};\n"
        : "+f"(c[0]), "+f"(c[1]), "+f"(c[2]), "+f"(c[3])
        : "r"(a[0]), "r"(a[1]), "r"(a[2]), "r"(a[3]), "r"(b[0]), "r"(b[1]));
}

__device__ __forceinline__ void ldsm_x4(uint32_t* r, uint32_t addr) {
    asm volatile(
        "ldmatrix.sync.aligned.m8n8.x4.shared.b16 {%0,%1,%2,%3}, [%4];"
        : "=r"(r[0]), "=r"(r[1]), "=r"(r[2]), "=r"(r[3]) : "r"(addr));
}

__device__ __forceinline__ void cp_async16(uint32_t smem_addr, const void* gptr) {
    asm volatile("cp.async.cg.shared.global [%0], [%1], 16;\n"
                 :: "r"(smem_addr), "l"(gptr));
}
__device__ __forceinline__ void cp_commit() {
    asm volatile("cp.async.commit_group;\n");
}
__device__ __forceinline__ void st_cs_f2(float* p, float a, float b) {
    asm volatile("st.global.cs.v2.f32 [%0], {%1,%2};\n"
                 :: "l"(p), "f"(a), "f"(b) : "memory");
}

__global__ __launch_bounds__(256, 2)
void gemm_f16_kernel(float* __restrict__ out, int N, int S) {
    extern __shared__ char sm[];
    const int tid  = threadIdx.x;
    const int lane = tid & 31;
    const int wid  = tid >> 5;
    const int wm   = wid & 1;        // 2 warp rows of 64
    const int wn   = wid >> 1;       // 4 warp cols of 32
    const int gid  = lane >> 2;      // 0..7
    const int tg   = lane & 3;       // 0..3

    const int m0 = blockIdx.x * TM;
    const int n0 = blockIdx.y * (TN * NJ);

    uint32_t sbase;
    asm("{ .reg .u64 t; cvta.to.shared.u64 t, %1; cvt.u32.u64 %0, t; }"
        : "=r"(sbase) : "l"(sm));
    const uint32_t Ab = sbase;

    // ---- A prefetch (once per CTA): 128 rows x 16 blocks ----
#pragma unroll
    for (int i = 0; i < 8; i++) {
        int f = tid + i * 256;
        int r = f >> 4, q = f & 15;
        uint32_t dst = Ab + (uint32_t)(r * 256 + ((q ^ (r & 7)) << 4));
        cp_async16(dst, g_x + (size_t)(m0 + r) * DIM + q * 8);
    }
    cp_commit();

    auto prefetchB = [&](int buf, int nt0) {
        uint32_t Bb = sbase + A_BYTES + (uint32_t)(buf * B_BYTES);
#pragma unroll
        for (int i = 0; i < 8; i++) {
            int f = tid + i * 256;
            int r = f >> 4, q = f & 15;
            uint32_t dst = Bb + (uint32_t)(r * 256 + ((q ^ (r & 7)) << 4));
            cp_async16(dst, g_w + (size_t)(nt0 + r) * DIM + q * 8);
        }
        cp_commit();
    };

    prefetchB(0, n0);
    prefetchB(1, n0 + TN);

    // ---- ldmatrix per-lane row assignments (proven rounds 8-15) ----
    const int rowA = (lane & 15);
    const int selA = (lane >> 4) & 1;
    const int rowB = (lane & 7) + ((lane & 16) >> 1);
    const int selB = (lane >> 3) & 1;
    const int swzA = rowA & 7;
    const int swzB = rowB & 7;

    uint32_t aAddr[4];
#pragma unroll
    for (int mi = 0; mi < 4; mi++)
        aAddr[mi] = Ab + (uint32_t)((wm * 64 + mi * 16 + rowA) * 256);

#pragma unroll
    for (int j = 0; j < NJ; j++) {
        if (j < NJ - 1) asm volatile("cp.async.wait_group 1;\n");
        else            asm volatile("cp.async.wait_group 0;\n");
        __syncthreads();

        const uint32_t Bb = sbase + A_BYTES + (uint32_t)((j & 1) * B_BYTES);
        uint32_t bAddr[2];
#pragma unroll
        for (int nj = 0; nj < 2; nj++)
            bAddr[nj] = Bb + (uint32_t)((wn * 32 + nj * 16 + rowB) * 256);

        float c[4][4][4];
#pragma unroll
        for (int mi = 0; mi < 4; mi++)
#pragma unroll
            for (int ni = 0; ni < 4; ni++)
#pragma unroll
                for (int jj = 0; jj < 4; jj++) c[mi][ni][jj] = 0.0f;

#pragma unroll
        for (int ks = 0; ks < 8; ks++) {
            const uint32_t offA = (uint32_t)(((2 * ks + selA) ^ swzA) << 4);
            const uint32_t offB = (uint32_t)(((2 * ks + selB) ^ swzB) << 4);
            uint32_t a[4][4], b[2][4];
#pragma unroll
            for (int mi = 0; mi < 4; mi++)
                ldsm_x4(a[mi], aAddr[mi] + offA);
#pragma unroll
            for (int nj = 0; nj < 2; nj++)
                ldsm_x4(b[nj], bAddr[nj] + offB);
#pragma unroll
            for (int mi = 0; mi < 4; mi++) {
#pragma unroll
                for (int ni = 0; ni < 4; ni++)
                    mma_f16(c[mi][ni], a[mi], &b[ni >> 1][(ni & 1) * 2]);
            }
        }
        __syncthreads();   // all reads of this B buffer done before refill

        if (j + 2 < NJ) prefetchB(j & 1, n0 + (j + 2) * TN);

        // ---- epilogue tile j: bias add + scattered streaming stores ----
        const int nt0 = n0 + j * TN;
#pragma unroll
        for (int mi = 0; mi < 4; mi++) {
            int r0 = m0 + wm * 64 + mi * 16 + gid;
#pragma unroll
            for (int ni = 0; ni < 4; ni++) {
                int col = nt0 + wn * 32 + ni * 8 + 2 * tg;
                float b0 = g_bias[col];
                float b1 = g_bias[col + 1];
                st_cs_f2(out + (size_t)r0 * S + col,
                         c[mi][ni][0] + b0, c[mi][ni][1] + b1);
                st_cs_f2(out + (size_t)(r0 + 8) * S + col,
                         c[mi][ni][2] + b0, c[mi][ni][3] + b1);
            }
        }
    }
}

// ---------------------------------------------------------------------------
extern "C" void kernel_launch(void* const* d_in, const int* in_sizes, int n_in,
                              void* d_out, int out_size) {
    const float* x    = (const float*)d_in[0];
    const float* w    = (const float*)d_in[1];
    const float* bias = (const float*)d_in[2];
    const void*  ids  = d_in[3];

    const int N = in_sizes[0] / DIM;   // 4096
    const int S = in_sizes[3];         // 32768

    static int smem_set = 0;
    if (!smem_set) {
        cudaFuncSetAttribute(gemm_f16_kernel,
                             cudaFuncAttributeMaxDynamicSharedMemorySize,
                             SM_TOTAL);
        smem_set = 1;
    }

    long long base  = (long long)N * (long long)S;
    long long extra = (long long)out_size - base;

    init_flag_kernel<<<1, 1>>>();
    detect_ids_kernel<<<128, 256>>>(ids, S);
    prep_kernel<<<1024, 256>>>(x, w, bias, ids, d_out, base, extra, N, S);

    dim3 grid(N / TM, S / (TN * NJ));
    gemm_f16_kernel<<<grid, 256, SM_TOTAL>>>((float*)d_out, N, S);
}

// round 17
// speedup vs baseline: 1.5127x; 1.5127x over previous
#include <cuda_runtime.h>
#include <cuda_fp16.h>
#include <cstdint>

// Problem constants: N=4096, D=128, S=32768, NUM_CLASS=500000.
#define DIM 128
#define MAX_S 32768
#define MAX_N 4096
#define NUM_CLASS_MAX 500000

// Scratch: fp16 operands + gathered fp32 bias.
static __device__ __half g_w[(size_t)MAX_S * DIM];
static __device__ __half g_x[(size_t)MAX_N * DIM];
static __device__ float g_bias[MAX_S];
static __device__ int g_ids_is64;

// ---------------------------------------------------------------------------
// Kernel 0a: reset dtype flag. Kernel 0b: parallel detect (benign-race store).
// ---------------------------------------------------------------------------
__global__ void init_flag_kernel() { g_ids_is64 = 1; }

__global__ void detect_ids_kernel(const void* __restrict__ ids, int S) {
    const long long* p = (const long long*)ids;
    int n64 = S / 2;
    int i = blockIdx.x * blockDim.x + threadIdx.x;
    int stride = gridDim.x * blockDim.x;
    int bad = 0;
    for (; i < n64; i += stride) {
        long long v = p[i];
        if (v < 0 || v >= NUM_CLASS_MAX) bad = 1;
    }
    if (__syncthreads_or(bad) && threadIdx.x == 0) g_ids_is64 = 0;
}

__device__ __forceinline__ long long read_id(const void* ids, int s) {
    long long id = g_ids_is64 ? ((const long long*)ids)[s]
                              : (long long)((const int*)ids)[s];
    if (id < 0 || id >= NUM_CLASS_MAX) id = 0;
    return id;
}

// ---------------------------------------------------------------------------
// Kernel 1 (fused): gather weight[ids]->g_w fp16 + bias; convert x->g_x fp16;
// ids pass-through into the output tail (runs BEFORE the GEMM).
// ---------------------------------------------------------------------------
__global__ void prep_kernel(const float* __restrict__ x,
                            const float* __restrict__ w,
                            const float* __restrict__ bias,
                            const void* __restrict__ ids,
                            void* out, long long base, long long extra,
                            int N, int S) {
    int warp = (blockIdx.x * blockDim.x + threadIdx.x) >> 5;
    int lane = threadIdx.x & 31;
    int nwarps = (gridDim.x * blockDim.x) >> 5;
    int total = S + N;
    for (int s = warp; s < total; s += nwarps) {
        const float4* src;
        __half2* dst;
        if (s < S) {
            long long id = read_id(ids, s);
            src = (const float4*)(w + (size_t)id * DIM);
            dst = (__half2*)(g_w + (size_t)s * DIM);
            if (lane == 0) g_bias[s] = bias[id];
        } else {
            int r = s - S;
            src = (const float4*)(x + (size_t)r * DIM);
            dst = (__half2*)(g_x + (size_t)r * DIM);
        }
        float4 v = src[lane];
        dst[lane * 2 + 0] = __float22half2_rn(make_float2(v.x, v.y));
        dst[lane * 2 + 1] = __float22half2_rn(make_float2(v.z, v.w));
    }
    if (extra > 0) {
        int gidx = blockIdx.x * blockDim.x + threadIdx.x;
        int gstride = gridDim.x * blockDim.x;
        for (int s = gidx; s < S; s += gstride) {
            long long id = read_id(ids, s);
            if (extra >= 2LL * S) {
                ((long long*)((float*)out + base))[s] = id;
            } else if (extra >= (long long)S) {
                ((float*)out)[base + s] = (float)id;
            }
        }
    }
}

// ---------------------------------------------------------------------------
// Kernel 2: fp16 GEMM, mma.m16n8k16 + ldmatrix, 256 threads (8 warps, 2x4),
// warp tile 64x32, 2 CTAs/SM (16 warps/SM). Each CTA: one resident A tile
// (128x128, 32KB) + FOUR consecutive 128-wide N-tiles with a 2x32KB B ring —
// B for tile j+1 streams while tile j computes; scattered st.cs.v2 epilogue.
// Rows hold full K=128 (256B); XOR-8 16B-block swizzle. (Measured-best GEMM
// config: 158.3us at normal clocks.)
// ---------------------------------------------------------------------------
#define TM 128
#define TN 128
#define NJ 4                                  // N-tiles per CTA
#define A_BYTES (TM * DIM * 2)                // 32768
#define B_BYTES (TN * DIM * 2)                // 32768
#define SM_TOTAL (A_BYTES + 2 * B_BYTES)      // 98304

__device__ __forceinline__ void mma_f16(float c[4], const uint32_t a[4],
                                        const uint32_t b[2]) {
    asm volatile(
        "mma.sync.aligned.m16n8k16.row.col.f32.f16.f16.f32 "
        "{%0,%1,%2,%3}, {%4,%5,%6,%7}, {%8,%9}, {%0,%1,%2,%3};\n"
        : "+f"(c[0]), "+f"(c[1]), "+f"(c[2]), "+f"(c[3])
        : "r"(a[0]), "r"(a[1]), "r"(a[2]), "r"(a[3]), "r"(b[0]), "r"(b[1]));
}

__device__ __forceinline__ void ldsm_x4(uint32_t* r, uint32_t addr) {
    asm volatile(
        "ldmatrix.sync.aligned.m8n8.x4.shared.b16 {%0,%1,%2,%3}, [%4];"
        : "=r"(r[0]), "=r"(r[1]), "=r"(r[2]), "=r"(r[3]) : "r"(addr));
}

__device__ __forceinline__ void cp_async16(uint32_t smem_addr, const void* gptr) {
    asm volatile("cp.async.cg.shared.global [%0], [%1], 16;\n"
                 :: "r"(smem_addr), "l"(gptr));
}
__device__ __forceinline__ void cp_commit() {
    asm volatile("cp.async.commit_group;\n");
}
__device__ __forceinline__ void st_cs_f2(float* p, float a, float b) {
    asm volatile("st.global.cs.v2.f32 [%0], {%1,%2};\n"
                 :: "l"(p), "f"(a), "f"(b) : "memory");
}

__global__ __launch_bounds__(256, 2)
void gemm_f16_kernel(float* __restrict__ out, int N, int S) {
    extern __shared__ char sm[];
    const int tid  = threadIdx.x;
    const int lane = tid & 31;
    const int wid  = tid >> 5;
    const int wm   = wid & 1;        // 2 warp rows of 64
    const int wn   = wid >> 1;       // 4 warp cols of 32
    const int gid  = lane >> 2;      // 0..7
    const int tg   = lane & 3;       // 0..3

    const int m0 = blockIdx.x * TM;
    const int n0 = blockIdx.y * (TN * NJ);

    uint32_t sbase;
    asm("{ .reg .u64 t; cvta.to.shared.u64 t, %1; cvt.u32.u64 %0, t; }"
        : "=r"(sbase) : "l"(sm));
    const uint32_t Ab = sbase;

    // ---- A prefetch (once per CTA): 128 rows x 16 blocks ----
#pragma unroll
    for (int i = 0; i < 8; i++) {
        int f = tid + i * 256;
        int r = f >> 4, q = f & 15;
        uint32_t dst = Ab + (uint32_t)(r * 256 + ((q ^ (r & 7)) << 4));
        cp_async16(dst, g_x + (size_t)(m0 + r) * DIM + q * 8);
    }
    cp_commit();

    auto prefetchB = [&](int buf, int nt0) {
        uint32_t Bb = sbase + A_BYTES + (uint32_t)(buf * B_BYTES);
#pragma unroll
        for (int i = 0; i < 8; i++) {
            int f = tid + i * 256;
            int r = f >> 4, q = f & 15;
            uint32_t dst = Bb + (uint32_t)(r * 256 + ((q ^ (r & 7)) << 4));
            cp_async16(dst, g_w + (size_t)(nt0 + r) * DIM + q * 8);
        }
        cp_commit();
    };

    prefetchB(0, n0);
    prefetchB(1, n0 + TN);

    // ---- ldmatrix per-lane row assignments (proven rounds 8-16) ----
    const int rowA = (lane & 15);
    const int selA = (lane >> 4) & 1;
    const int rowB = (lane & 7) + ((lane & 16) >> 1);
    const int selB = (lane >> 3) & 1;
    const int swzA = rowA & 7;
    const int swzB = rowB & 7;

    uint32_t aAddr[4];
#pragma unroll
    for (int mi = 0; mi < 4; mi++)
        aAddr[mi] = Ab + (uint32_t)((wm * 64 + mi * 16 + rowA) * 256);

#pragma unroll
    for (int j = 0; j < NJ; j++) {
        if (j < NJ - 1) asm volatile("cp.async.wait_group 1;\n");
        else            asm volatile("cp.async.wait_group 0;\n");
        __syncthreads();

        const uint32_t Bb = sbase + A_BYTES + (uint32_t)((j & 1) * B_BYTES);
        uint32_t bAddr[2];
#pragma unroll
        for (int nj = 0; nj < 2; nj++)
            bAddr[nj] = Bb + (uint32_t)((wn * 32 + nj * 16 + rowB) * 256);

        float c[4][4][4];
#pragma unroll
        for (int mi = 0; mi < 4; mi++)
#pragma unroll
            for (int ni = 0; ni < 4; ni++)
#pragma unroll
                for (int jj = 0; jj < 4; jj++) c[mi][ni][jj] = 0.0f;

#pragma unroll
        for (int ks = 0; ks < 8; ks++) {
            const uint32_t offA = (uint32_t)(((2 * ks + selA) ^ swzA) << 4);
            const uint32_t offB = (uint32_t)(((2 * ks + selB) ^ swzB) << 4);
            uint32_t a[4][4], b[2][4];
#pragma unroll
            for (int mi = 0; mi < 4; mi++)
                ldsm_x4(a[mi], aAddr[mi] + offA);
#pragma unroll
            for (int nj = 0; nj < 2; nj++)
                ldsm_x4(b[nj], bAddr[nj] + offB);
#pragma unroll
            for (int mi = 0; mi < 4; mi++) {
#pragma unroll
                for (int ni = 0; ni < 4; ni++)
                    mma_f16(c[mi][ni], a[mi], &b[ni >> 1][(ni & 1) * 2]);
            }
        }
        __syncthreads();   // all reads of this B buffer done before refill

        if (j + 2 < NJ) prefetchB(j & 1, n0 + (j + 2) * TN);

        // ---- epilogue tile j: bias add + scattered streaming stores ----
        const int nt0 = n0 + j * TN;
#pragma unroll
        for (int mi = 0; mi < 4; mi++) {
            int r0 = m0 + wm * 64 + mi * 16 + gid;
#pragma unroll
            for (int ni = 0; ni < 4; ni++) {
                int col = nt0 + wn * 32 + ni * 8 + 2 * tg;
                float b0 = g_bias[col];
                float b1 = g_bias[col + 1];
                st_cs_f2(out + (size_t)r0 * S + col,
                         c[mi][ni][0] + b0, c[mi][ni][1] + b1);
                st_cs_f2(out + (size_t)(r0 + 8) * S + col,
                         c[mi][ni][2] + b0, c[mi][ni][3] + b1);
            }
        }
    }
}

// ---------------------------------------------------------------------------
extern "C" void kernel_launch(void* const* d_in, const int* in_sizes, int n_in,
                              void* d_out, int out_size) {
    const float* x    = (const float*)d_in[0];
    const float* w    = (const float*)d_in[1];
    const float* bias = (const float*)d_in[2];
    const void*  ids  = d_in[3];

    const int N = in_sizes[0] / DIM;   // 4096
    const int S = in_sizes[3];         // 32768

    static int smem_set = 0;
    if (!smem_set) {
        cudaFuncSetAttribute(gemm_f16_kernel,
                             cudaFuncAttributeMaxDynamicSharedMemorySize,
                             SM_TOTAL);
        smem_set = 1;
    }

    long long base  = (long long)N * (long long)S;
    long long extra = (long long)out_size - base;

    init_flag_kernel<<<1, 1>>>();
    detect_ids_kernel<<<128, 256>>>(ids, S);
    prep_kernel<<<1024, 256>>>(x, w, bias, ids, d_out, base, extra, N, S);

    dim3 grid(N / TM, S / (TN * NJ));
    gemm_f16_kernel<<<grid, 256, SM_TOTAL>>>((float*)d_out, N, S);
}